// round 9
// baseline (speedup 1.0000x reference)
#include <cuda_runtime.h>
#include <cstdint>
#include <cstddef>

// Problem dims (fixed per reference)
#define BB 256
#define TT 512
#define II 64
#define HH 128
#define GG 512   // 4*H

typedef unsigned long long ull;

// Scratch for precomputed input-gate projections: [B, T, 4H] fp32 = 256 MB.
__device__ float g_xg[(size_t)BB * TT * GG];

__device__ __forceinline__ float fsig(float x) {
    return __fdividef(1.f, 1.f + __expf(-x));
}
__device__ __forceinline__ float ftanh(float x) {
    float e = __expf(2.f * x);
    return 1.f - __fdividef(2.f, e + 1.f);
}

// Packed f32x2 ops (sm_103a; ptxas never auto-fuses these)
__device__ __forceinline__ ull fma2(ull a, ull b, ull c) {
    ull d;
    asm("fma.rn.f32x2 %0, %1, %2, %3;" : "=l"(d) : "l"(a), "l"(b), "l"(c));
    return d;
}
__device__ __forceinline__ ull add2(ull a, ull b) {
    ull d;
    asm("add.rn.f32x2 %0, %1, %2;" : "=l"(d) : "l"(a), "l"(b));
    return d;
}
__device__ __forceinline__ ull pack2(float x, float y) {
    ull r;
    asm("mov.b64 %0, {%1, %2};" : "=l"(r) : "f"(x), "f"(y));
    return r;
}
__device__ __forceinline__ float hsum2(ull a) {
    uint2 u = *reinterpret_cast<uint2*>(&a);
    return __uint_as_float(u.x) + __uint_as_float(u.y);
}
__device__ __forceinline__ float lo2(ull a) { return __uint_as_float((unsigned)a); }
__device__ __forceinline__ float hi2(ull a) { return __uint_as_float((unsigned)(a >> 32)); }

__device__ __forceinline__ void cp_async4(unsigned dst, const float* src) {
    asm volatile("cp.async.ca.shared.global [%0], [%1], 4;" :: "r"(dst), "l"(src));
}
__device__ __forceinline__ void cp_commit() {
    asm volatile("cp.async.commit_group;" ::: "memory");
}
__device__ __forceinline__ void cp_wait0() {
    asm volatile("cp.async.wait_group 0;" ::: "memory");
}

// ---------------------------------------------------------------------------
// Kernel 1: x_gates GEMM, f32x2-packed, PERSISTENT blocks, 2-stage cp.async
// pipeline on the X tile (next tile's loads overlap the current compute).
// ---------------------------------------------------------------------------
#define NTILES 2048
#define XS_STRIDE 68
#define XS_SIZE (64 * XS_STRIDE)

__global__ __launch_bounds__(512, 1) void xg_gemm(
    const float* __restrict__ X,
    const float* __restrict__ Wih,
    const float* __restrict__ bih,
    const float* __restrict__ bhh)
{
    extern __shared__ __align__(16) float sm[];
    float* Xs0 = sm;                       // [64][68] buffer 0
    float* Xs1 = sm + XS_SIZE;             // [64][68] buffer 1
    float* Ws  = sm + 2 * XS_SIZE;         // [64][516]
    float* bs  = Ws + 64 * 516;            // [512]
    const int tid = threadIdx.x;

    bs[tid] = bih[tid] + bhh[tid];
    for (int idx = tid; idx < 512 * 64; idx += 512) {
        int n = idx >> 6, k = idx & 63;
        Ws[k * 516 + n] = Wih[n * II + k];
    }

    const int ni = tid & 63, mi = tid >> 6;
    const int nb = ni * 8,  mb = mi * 8;

    // Per-thread transpose-load mapping: idx = tid + 512*i -> (m, k)
    const int lm[8] = { (tid) >> 6,        (tid + 512) >> 6,  (tid + 1024) >> 6, (tid + 1536) >> 6,
                        (tid + 2048) >> 6, (tid + 2560) >> 6, (tid + 3072) >> 6, (tid + 3584) >> 6 };
    const int lk = tid & 63;

    unsigned xs0_base = (unsigned)__cvta_generic_to_shared(Xs0);
    unsigned xs1_base = (unsigned)__cvta_generic_to_shared(Xs1);

    // Prologue: issue loads for my first tile into buffer 0
    int tile = blockIdx.x;
    if (tile < NTILES) {
        #pragma unroll
        for (int i = 0; i < 8; i++)
            cp_async4(xs0_base + (unsigned)((lk * XS_STRIDE + lm[i]) * 4),
                      &X[(size_t)(tile * 64 + lm[i]) * II + lk]);
    }
    cp_commit();

    int buf = 0;
    for (; tile < NTILES; tile += gridDim.x) {
        cp_wait0();          // my async loads for current buffer complete
        __syncthreads();     // everyone's loads done + previous compute done

        // Issue next tile's loads into the other buffer (overlaps compute)
        int ntile = tile + gridDim.x;
        unsigned obase = buf ? xs0_base : xs1_base;
        if (ntile < NTILES) {
            #pragma unroll
            for (int i = 0; i < 8; i++)
                cp_async4(obase + (unsigned)((lk * XS_STRIDE + lm[i]) * 4),
                          &X[(size_t)(ntile * 64 + lm[i]) * II + lk]);
        }
        cp_commit();

        const float* Xs = buf ? Xs1 : Xs0;
        const int m0 = tile * 64;

        ull acc2[4][8];
        #pragma unroll
        for (int n = 0; n < 8; n++) {
            float bv = bs[nb + n];
            ull bp = pack2(bv, bv);
            #pragma unroll
            for (int mp = 0; mp < 4; mp++) acc2[mp][n] = bp;
        }

        #pragma unroll 4
        for (int k = 0; k < 64; k++) {
            ulonglong2 a01 = *(const ulonglong2*)&Xs[k * XS_STRIDE + mb];
            ulonglong2 a23 = *(const ulonglong2*)&Xs[k * XS_STRIDE + mb + 4];
            ull a[4] = {a01.x, a01.y, a23.x, a23.y};
            float4 b0 = *(const float4*)&Ws[k * 516 + nb];
            float4 b1 = *(const float4*)&Ws[k * 516 + nb + 4];
            float bv[8] = {b0.x, b0.y, b0.z, b0.w, b1.x, b1.y, b1.z, b1.w};
            #pragma unroll
            for (int n = 0; n < 8; n++) {
                ull bb = pack2(bv[n], bv[n]);
                #pragma unroll
                for (int mp = 0; mp < 4; mp++)
                    acc2[mp][n] = fma2(a[mp], bb, acc2[mp][n]);
            }
        }

        #pragma unroll
        for (int mp = 0; mp < 4; mp++) {
            size_t row0 = (size_t)(m0 + mb + 2 * mp);
            float4* o0 = (float4*)&g_xg[row0 * GG + nb];
            float4* o1 = (float4*)&g_xg[(row0 + 1) * GG + nb];
            o0[0] = make_float4(lo2(acc2[mp][0]), lo2(acc2[mp][1]), lo2(acc2[mp][2]), lo2(acc2[mp][3]));
            o0[1] = make_float4(lo2(acc2[mp][4]), lo2(acc2[mp][5]), lo2(acc2[mp][6]), lo2(acc2[mp][7]));
            o1[0] = make_float4(hi2(acc2[mp][0]), hi2(acc2[mp][1]), hi2(acc2[mp][2]), hi2(acc2[mp][3]));
            o1[1] = make_float4(hi2(acc2[mp][4]), hi2(acc2[mp][5]), hi2(acc2[mp][6]), hi2(acc2[mp][7]));
        }
        buf ^= 1;
    }
}

// ---------------------------------------------------------------------------
// Kernel 2: LSTM scan — R4's proven split (KREG=80) + R8's double-buffered h
// and 2-warp-group named barrier. 128 blocks x 256 threads; thread owns gates
// tid & tid+256 for both batches; 8 independent fma2 chains.
// ---------------------------------------------------------------------------
#define KREG 80                  // k-values per gate held in registers
#define QSH  12                  // (128-KREG)/4 : ulonglong2 smem weight loads

__global__ __launch_bounds__(256, 1) void lstm_scan(
    const float* __restrict__ hprev,
    const float* __restrict__ cprev,
    const float* __restrict__ Whh,
    float* __restrict__ out)
{
    extern __shared__ __align__(16) float smdyn[];
    ulonglong2* wA = (ulonglong2*)smdyn;         // [QSH][256]
    ulonglong2* wB = wA + QSH * 256;             // [QSH][256]
    float* hbuf = (float*)(wB + QSH * 256);      // [2 buf][2 batch][128]
    float* gsm  = hbuf + 2 * 2 * 128;            // [2][512]

    const int tid = threadIdx.x;
    const int b0  = blockIdx.x * 2;
    const int gA  = tid;
    const int gB  = tid + 256;
    const int barid = 1 + ((tid >> 5) & 3);      // 2-warp group {w, w+4}

    // Stage smem weight tail (k = KREG..127) for both gates
    #pragma unroll
    for (int q = 0; q < QSH; q++) {
        wA[q * 256 + tid] = *(const ulonglong2*)&Whh[gA * HH + KREG + 4 * q];
        wB[q * 256 + tid] = *(const ulonglong2*)&Whh[gB * HH + KREG + 4 * q];
    }

    // Register weights: 40 packed pairs per gate
    ull wrA[KREG / 2], wrB[KREG / 2];
    #pragma unroll
    for (int p = 0; p < KREG / 2; p++) {
        wrA[p] = *(const ull*)&Whh[gA * HH + 2 * p];
        wrB[p] = *(const ull*)&Whh[gB * HH + 2 * p];
    }

    // h double buffers
    float* hc0 = hbuf;             // current, batch 0
    float* hc1 = hbuf + 128;       // current, batch 1
    float* hn0 = hbuf + 256;       // next,    batch 0
    float* hn1 = hbuf + 384;       // next,    batch 1

    // Init h, c : thread owns (b = tid>>7, j = tid&127)
    const int b = tid >> 7, j = tid & 127;
    float h = hprev[(b0 + b) * HH + j];
    float c = cprev[(b0 + b) * HH + j];
    (b ? hc1 : hc0)[j] = h;
    __syncthreads();

    // Incremental x pointers (avoid per-step 64-bit address math)
    const float* xp0 = g_xg + (size_t)b0 * TT * GG + tid;
    const float* xp1 = xp0 + (size_t)TT * GG;

    // Prefetch t=0 x values
    float x00 = xp0[0], x01 = xp0[256];
    float x10 = xp1[0], x11 = xp1[256];

    for (int t = 0; t < TT; t++) {
        // Prefetch next step's x (consumed one full GEMV later)
        const float* np0 = xp0 + ((t + 1 < TT) ? GG : 0);
        const float* np1 = xp1 + ((t + 1 < TT) ? GG : 0);
        float n00 = np0[0], n01 = np0[256];
        float n10 = np1[0], n11 = np1[256];

        // 8 independent accumulator chains: {gate A,B} x {batch 0,1} x {x,y}
        ull aA0x = 0, aA0y = 0, aA1x = 0, aA1y = 0;
        ull aB0x = 0, aB0y = 0, aB1x = 0, aB1y = 0;

        // k = 0..KREG-1 : register weights
        #pragma unroll
        for (int q = 0; q < KREG / 4; q++) {
            ulonglong2 h0 = *(const ulonglong2*)&hc0[4 * q];
            ulonglong2 h1 = *(const ulonglong2*)&hc1[4 * q];
            ull w0 = wrA[2 * q], w1 = wrA[2 * q + 1];
            ull v0 = wrB[2 * q], v1 = wrB[2 * q + 1];
            aA0x = fma2(w0, h0.x, aA0x);  aA0y = fma2(w1, h0.y, aA0y);
            aA1x = fma2(w0, h1.x, aA1x);  aA1y = fma2(w1, h1.y, aA1y);
            aB0x = fma2(v0, h0.x, aB0x);  aB0y = fma2(v1, h0.y, aB0y);
            aB1x = fma2(v0, h1.x, aB1x);  aB1y = fma2(v1, h1.y, aB1y);
        }
        // k = KREG..127 : smem weights
        #pragma unroll
        for (int q = 0; q < QSH; q++) {
            ulonglong2 h0 = *(const ulonglong2*)&hc0[KREG + 4 * q];
            ulonglong2 h1 = *(const ulonglong2*)&hc1[KREG + 4 * q];
            ulonglong2 wa = wA[q * 256 + tid];
            ulonglong2 wb = wB[q * 256 + tid];
            aA0x = fma2(wa.x, h0.x, aA0x);  aA0y = fma2(wa.y, h0.y, aA0y);
            aA1x = fma2(wa.x, h1.x, aA1x);  aA1y = fma2(wa.y, h1.y, aA1y);
            aB0x = fma2(wb.x, h0.x, aB0x);  aB0y = fma2(wb.y, h0.y, aB0y);
            aB1x = fma2(wb.x, h1.x, aB1x);  aB1y = fma2(wb.y, h1.y, aB1y);
        }

        gsm[tid]             = x00 + hsum2(add2(aA0x, aA0y));
        gsm[256 + tid]       = x01 + hsum2(add2(aB0x, aB0y));
        gsm[512 + tid]       = x10 + hsum2(add2(aA1x, aA1y));
        gsm[512 + 256 + tid] = x11 + hsum2(add2(aB1x, aB1y));

        // Group barrier: cells {j, j+128} <- gates from threads {j, j+128}
        // = warps {w, w+4} only; gsm slots are group-private. h hazard gone.
        asm volatile("bar.sync %0, %1;" :: "r"(barid), "r"(64) : "memory");

        // Cell update: all 256 threads, one (batch, cell) each; write h_next
        {
            const float* gb = gsm + b * 512;
            float ig = fsig(gb[j]);             // PyTorch order: i, f, g, o
            float fg = fsig(gb[j + 128]);
            float gg = ftanh(gb[j + 256]);
            float og = fsig(gb[j + 384]);
            c = fg * c + ig * gg;
            h = og * ftanh(c);
            (b ? hn1 : hn0)[j] = h;
            out[((size_t)(b0 + b) * TT + t) * HH + j] = h;
        }
        __syncthreads();   // hn published; all GEMV reads of hc done

        // Swap buffers
        float* s0 = hc0; hc0 = hn0; hn0 = s0;
        float* s1 = hc1; hc1 = hn1; hn1 = s1;

        xp0 = np0; xp1 = np1;
        x00 = n00; x01 = n01; x10 = n10; x11 = n11;
    }

    // h_last, c_last appended after outputs (thread-local h, c)
    {
        size_t base = (size_t)BB * TT * HH;
        out[base + (b0 + b) * HH + j] = h;
        out[base + (size_t)BB * HH + (b0 + b) * HH + j] = c;
    }
}

// ---------------------------------------------------------------------------
extern "C" void kernel_launch(void* const* d_in, const int* in_sizes, int n_in,
                              void* d_out, int out_size)
{
    const float* inputs = (const float*)d_in[0];
    const float* hprev  = (const float*)d_in[1];
    const float* cprev  = (const float*)d_in[2];
    const float* Wih    = (const float*)d_in[3];
    const float* Whh    = (const float*)d_in[4];
    const float* bih    = (const float*)d_in[5];
    const float* bhh    = (const float*)d_in[6];
    float* out = (float*)d_out;
    (void)in_sizes; (void)n_in; (void)out_size;

    const size_t smem1 = (size_t)(2 * XS_SIZE + 64 * 516 + 512) * sizeof(float);  // ~165 KB
    const size_t smem2 = (size_t)(2 * QSH * 256) * sizeof(ulonglong2)
                       + (size_t)(2 * 2 * 128 + 2 * 512) * sizeof(float);         // ~104 KB
    cudaFuncSetAttribute(xg_gemm,   cudaFuncAttributeMaxDynamicSharedMemorySize, (int)smem1);
    cudaFuncSetAttribute(lstm_scan, cudaFuncAttributeMaxDynamicSharedMemorySize, (int)smem2);

    xg_gemm  <<<148, 512, smem1>>>(inputs, Wih, bih, bhh);
    lstm_scan<<<128, 256, smem2>>>(hprev, cprev, Whh, out);
}

// round 10
// speedup vs baseline: 1.2945x; 1.2945x over previous
#include <cuda_runtime.h>
#include <cstdint>
#include <cstddef>

// Problem dims (fixed per reference)
#define BB 256
#define TT 512
#define II 64
#define HH 128
#define GG 512   // 4*H

typedef unsigned long long ull;

// Scratch for precomputed input-gate projections: [B, T, 4H] fp32 = 256 MB.
__device__ float g_xg[(size_t)BB * TT * GG];

__device__ __forceinline__ float fsig(float x) {
    return __fdividef(1.f, 1.f + __expf(-x));
}
__device__ __forceinline__ float ftanh(float x) {
    float e = __expf(2.f * x);
    return 1.f - __fdividef(2.f, e + 1.f);
}

// Packed f32x2 ops (sm_103a; ptxas never auto-fuses these)
__device__ __forceinline__ ull fma2(ull a, ull b, ull c) {
    ull d;
    asm("fma.rn.f32x2 %0, %1, %2, %3;" : "=l"(d) : "l"(a), "l"(b), "l"(c));
    return d;
}
__device__ __forceinline__ ull add2(ull a, ull b) {
    ull d;
    asm("add.rn.f32x2 %0, %1, %2;" : "=l"(d) : "l"(a), "l"(b));
    return d;
}
__device__ __forceinline__ ull pack2(float x, float y) {
    ull r;
    asm("mov.b64 %0, {%1, %2};" : "=l"(r) : "f"(x), "f"(y));
    return r;
}
__device__ __forceinline__ float hsum2(ull a) {
    uint2 u = *reinterpret_cast<uint2*>(&a);
    return __uint_as_float(u.x) + __uint_as_float(u.y);
}
__device__ __forceinline__ float lo2(ull a) { return __uint_as_float((unsigned)a); }
__device__ __forceinline__ float hi2(ull a) { return __uint_as_float((unsigned)(a >> 32)); }

__device__ __forceinline__ void cp_async4(unsigned dst, const float* src) {
    asm volatile("cp.async.ca.shared.global [%0], [%1], 4;" :: "r"(dst), "l"(src));
}
__device__ __forceinline__ void cp_commit() {
    asm volatile("cp.async.commit_group;" ::: "memory");
}
__device__ __forceinline__ void cp_wait0() {
    asm volatile("cp.async.wait_group 0;" ::: "memory");
}

// ---------------------------------------------------------------------------
// Kernel 1: x_gates GEMM — unchanged from R9 (cp.async pipeline, 218 us).
// ---------------------------------------------------------------------------
#define NTILES 2048
#define XS_STRIDE 68
#define XS_SIZE (64 * XS_STRIDE)

__global__ __launch_bounds__(512, 1) void xg_gemm(
    const float* __restrict__ X,
    const float* __restrict__ Wih,
    const float* __restrict__ bih,
    const float* __restrict__ bhh)
{
    extern __shared__ __align__(16) float sm[];
    float* Xs0 = sm;                       // [64][68] buffer 0
    float* Xs1 = sm + XS_SIZE;             // [64][68] buffer 1
    float* Ws  = sm + 2 * XS_SIZE;         // [64][516]
    float* bs  = Ws + 64 * 516;            // [512]
    const int tid = threadIdx.x;

    bs[tid] = bih[tid] + bhh[tid];
    for (int idx = tid; idx < 512 * 64; idx += 512) {
        int n = idx >> 6, k = idx & 63;
        Ws[k * 516 + n] = Wih[n * II + k];
    }

    const int ni = tid & 63, mi = tid >> 6;
    const int nb = ni * 8,  mb = mi * 8;

    const int lm[8] = { (tid) >> 6,        (tid + 512) >> 6,  (tid + 1024) >> 6, (tid + 1536) >> 6,
                        (tid + 2048) >> 6, (tid + 2560) >> 6, (tid + 3072) >> 6, (tid + 3584) >> 6 };
    const int lk = tid & 63;

    unsigned xs0_base = (unsigned)__cvta_generic_to_shared(Xs0);
    unsigned xs1_base = (unsigned)__cvta_generic_to_shared(Xs1);

    int tile = blockIdx.x;
    if (tile < NTILES) {
        #pragma unroll
        for (int i = 0; i < 8; i++)
            cp_async4(xs0_base + (unsigned)((lk * XS_STRIDE + lm[i]) * 4),
                      &X[(size_t)(tile * 64 + lm[i]) * II + lk]);
    }
    cp_commit();

    int buf = 0;
    for (; tile < NTILES; tile += gridDim.x) {
        cp_wait0();
        __syncthreads();

        int ntile = tile + gridDim.x;
        unsigned obase = buf ? xs0_base : xs1_base;
        if (ntile < NTILES) {
            #pragma unroll
            for (int i = 0; i < 8; i++)
                cp_async4(obase + (unsigned)((lk * XS_STRIDE + lm[i]) * 4),
                          &X[(size_t)(ntile * 64 + lm[i]) * II + lk]);
        }
        cp_commit();

        const float* Xs = buf ? Xs1 : Xs0;
        const int m0 = tile * 64;

        ull acc2[4][8];
        #pragma unroll
        for (int n = 0; n < 8; n++) {
            float bv = bs[nb + n];
            ull bp = pack2(bv, bv);
            #pragma unroll
            for (int mp = 0; mp < 4; mp++) acc2[mp][n] = bp;
        }

        #pragma unroll 4
        for (int k = 0; k < 64; k++) {
            ulonglong2 a01 = *(const ulonglong2*)&Xs[k * XS_STRIDE + mb];
            ulonglong2 a23 = *(const ulonglong2*)&Xs[k * XS_STRIDE + mb + 4];
            ull a[4] = {a01.x, a01.y, a23.x, a23.y};
            float4 b0 = *(const float4*)&Ws[k * 516 + nb];
            float4 b1 = *(const float4*)&Ws[k * 516 + nb + 4];
            float bv[8] = {b0.x, b0.y, b0.z, b0.w, b1.x, b1.y, b1.z, b1.w};
            #pragma unroll
            for (int n = 0; n < 8; n++) {
                ull bb = pack2(bv[n], bv[n]);
                #pragma unroll
                for (int mp = 0; mp < 4; mp++)
                    acc2[mp][n] = fma2(a[mp], bb, acc2[mp][n]);
            }
        }

        #pragma unroll
        for (int mp = 0; mp < 4; mp++) {
            size_t row0 = (size_t)(m0 + mb + 2 * mp);
            float4* o0 = (float4*)&g_xg[row0 * GG + nb];
            float4* o1 = (float4*)&g_xg[(row0 + 1) * GG + nb];
            o0[0] = make_float4(lo2(acc2[mp][0]), lo2(acc2[mp][1]), lo2(acc2[mp][2]), lo2(acc2[mp][3]));
            o0[1] = make_float4(lo2(acc2[mp][4]), lo2(acc2[mp][5]), lo2(acc2[mp][6]), lo2(acc2[mp][7]));
            o1[0] = make_float4(hi2(acc2[mp][0]), hi2(acc2[mp][1]), hi2(acc2[mp][2]), hi2(acc2[mp][3]));
            o1[1] = make_float4(hi2(acc2[mp][4]), hi2(acc2[mp][5]), hi2(acc2[mp][6]), hi2(acc2[mp][7]));
        }
        buf ^= 1;
    }
}

// ---------------------------------------------------------------------------
// Kernel 2: LSTM scan — R4 body (KREG=80, 8 indep chains, INDEXED x prefetch;
// R9 proved loop-carried pointers kill it) + R8's double-buffered h and
// 2-warp-group named barrier. 128 blocks x 256 threads.
// ---------------------------------------------------------------------------
#define KREG 80                  // k-values per gate held in registers
#define QSH  12                  // (128-KREG)/4 : ulonglong2 smem weight loads

__global__ __launch_bounds__(256, 1) void lstm_scan(
    const float* __restrict__ hprev,
    const float* __restrict__ cprev,
    const float* __restrict__ Whh,
    float* __restrict__ out)
{
    extern __shared__ __align__(16) float smdyn[];
    ulonglong2* wA = (ulonglong2*)smdyn;         // [QSH][256]
    ulonglong2* wB = wA + QSH * 256;             // [QSH][256]
    float* hbuf = (float*)(wB + QSH * 256);      // [2 buf][2 batch][128]
    float* gsm  = hbuf + 2 * 2 * 128;            // [2][512]

    const int tid = threadIdx.x;
    const int b0  = blockIdx.x * 2;
    const int gA  = tid;
    const int gB  = tid + 256;
    const int barid = 1 + ((tid >> 5) & 3);      // 2-warp group {w, w+4}

    // Stage smem weight tail (k = KREG..127) for both gates
    #pragma unroll
    for (int q = 0; q < QSH; q++) {
        wA[q * 256 + tid] = *(const ulonglong2*)&Whh[gA * HH + KREG + 4 * q];
        wB[q * 256 + tid] = *(const ulonglong2*)&Whh[gB * HH + KREG + 4 * q];
    }

    // Register weights: 40 packed pairs per gate
    ull wrA[KREG / 2], wrB[KREG / 2];
    #pragma unroll
    for (int p = 0; p < KREG / 2; p++) {
        wrA[p] = *(const ull*)&Whh[gA * HH + 2 * p];
        wrB[p] = *(const ull*)&Whh[gB * HH + 2 * p];
    }

    // h double buffers
    float* hc0 = hbuf;             // current, batch 0
    float* hc1 = hbuf + 128;       // current, batch 1
    float* hn0 = hbuf + 256;       // next,    batch 0
    float* hn1 = hbuf + 384;       // next,    batch 1

    // Init h, c : thread owns (b = tid>>7, j = tid&127)
    const int b = tid >> 7, j = tid & 127;
    float h = hprev[(b0 + b) * HH + j];
    float c = cprev[(b0 + b) * HH + j];
    (b ? hc1 : hc0)[j] = h;
    __syncthreads();

    const float* xb0 = g_xg + (size_t)b0 * TT * GG;
    const float* xb1 = xb0 + (size_t)TT * GG;

    // Prefetch t=0 x values (indexed addressing — R4 style)
    float x00 = xb0[tid], x01 = xb0[256 + tid];
    float x10 = xb1[tid], x11 = xb1[256 + tid];

    for (int t = 0; t < TT; t++) {
        // Prefetch next step's x (consumed one full GEMV later)
        size_t noff = (size_t)(t + 1 < TT ? t + 1 : t) * GG;
        float n00 = xb0[noff + tid], n01 = xb0[noff + 256 + tid];
        float n10 = xb1[noff + tid], n11 = xb1[noff + 256 + tid];

        // 8 independent accumulator chains: {gate A,B} x {batch 0,1} x {x,y}
        ull aA0x = 0, aA0y = 0, aA1x = 0, aA1y = 0;
        ull aB0x = 0, aB0y = 0, aB1x = 0, aB1y = 0;

        // k = 0..KREG-1 : register weights
        #pragma unroll
        for (int q = 0; q < KREG / 4; q++) {
            ulonglong2 h0 = *(const ulonglong2*)&hc0[4 * q];
            ulonglong2 h1 = *(const ulonglong2*)&hc1[4 * q];
            ull w0 = wrA[2 * q], w1 = wrA[2 * q + 1];
            ull v0 = wrB[2 * q], v1 = wrB[2 * q + 1];
            aA0x = fma2(w0, h0.x, aA0x);  aA0y = fma2(w1, h0.y, aA0y);
            aA1x = fma2(w0, h1.x, aA1x);  aA1y = fma2(w1, h1.y, aA1y);
            aB0x = fma2(v0, h0.x, aB0x);  aB0y = fma2(v1, h0.y, aB0y);
            aB1x = fma2(v0, h1.x, aB1x);  aB1y = fma2(v1, h1.y, aB1y);
        }
        // k = KREG..127 : smem weights
        #pragma unroll
        for (int q = 0; q < QSH; q++) {
            ulonglong2 h0 = *(const ulonglong2*)&hc0[KREG + 4 * q];
            ulonglong2 h1 = *(const ulonglong2*)&hc1[KREG + 4 * q];
            ulonglong2 wa = wA[q * 256 + tid];
            ulonglong2 wb = wB[q * 256 + tid];
            aA0x = fma2(wa.x, h0.x, aA0x);  aA0y = fma2(wa.y, h0.y, aA0y);
            aA1x = fma2(wa.x, h1.x, aA1x);  aA1y = fma2(wa.y, h1.y, aA1y);
            aB0x = fma2(wb.x, h0.x, aB0x);  aB0y = fma2(wb.y, h0.y, aB0y);
            aB1x = fma2(wb.x, h1.x, aB1x);  aB1y = fma2(wb.y, h1.y, aB1y);
        }

        gsm[tid]             = x00 + hsum2(add2(aA0x, aA0y));
        gsm[256 + tid]       = x01 + hsum2(add2(aB0x, aB0y));
        gsm[512 + tid]       = x10 + hsum2(add2(aA1x, aA1y));
        gsm[512 + 256 + tid] = x11 + hsum2(add2(aB1x, aB1y));

        // Group barrier: cells {j, j+128} <- gates from threads {j, j+128}
        // = warps {w, w+4} only; gsm slots are group-private. h hazard gone
        // (update writes hn, GEMV read hc).
        asm volatile("bar.sync %0, %1;" :: "r"(barid), "r"(64) : "memory");

        // Cell update: all 256 threads, one (batch, cell) each; write h_next
        {
            const float* gb = gsm + b * 512;
            float ig = fsig(gb[j]);             // PyTorch order: i, f, g, o
            float fg = fsig(gb[j + 128]);
            float gg = ftanh(gb[j + 256]);
            float og = fsig(gb[j + 384]);
            c = fg * c + ig * gg;
            h = og * ftanh(c);
            (b ? hn1 : hn0)[j] = h;
            out[((size_t)(b0 + b) * TT + t) * HH + j] = h;
        }
        __syncthreads();   // hn published; all GEMV reads of hc done

        // Swap buffers
        float* s0 = hc0; hc0 = hn0; hn0 = s0;
        float* s1 = hc1; hc1 = hn1; hn1 = s1;

        x00 = n00; x01 = n01; x10 = n10; x11 = n11;
    }

    // h_last, c_last appended after outputs (thread-local h, c)
    {
        size_t base = (size_t)BB * TT * HH;
        out[base + (b0 + b) * HH + j] = h;
        out[base + (size_t)BB * HH + (b0 + b) * HH + j] = c;
    }
}

// ---------------------------------------------------------------------------
extern "C" void kernel_launch(void* const* d_in, const int* in_sizes, int n_in,
                              void* d_out, int out_size)
{
    const float* inputs = (const float*)d_in[0];
    const float* hprev  = (const float*)d_in[1];
    const float* cprev  = (const float*)d_in[2];
    const float* Wih    = (const float*)d_in[3];
    const float* Whh    = (const float*)d_in[4];
    const float* bih    = (const float*)d_in[5];
    const float* bhh    = (const float*)d_in[6];
    float* out = (float*)d_out;
    (void)in_sizes; (void)n_in; (void)out_size;

    const size_t smem1 = (size_t)(2 * XS_SIZE + 64 * 516 + 512) * sizeof(float);  // ~165 KB
    const size_t smem2 = (size_t)(2 * QSH * 256) * sizeof(ulonglong2)
                       + (size_t)(2 * 2 * 128 + 2 * 512) * sizeof(float);         // ~104 KB
    cudaFuncSetAttribute(xg_gemm,   cudaFuncAttributeMaxDynamicSharedMemorySize, (int)smem1);
    cudaFuncSetAttribute(lstm_scan, cudaFuncAttributeMaxDynamicSharedMemorySize, (int)smem2);

    xg_gemm  <<<148, 512, smem1>>>(inputs, Wih, bih, bhh);
    lstm_scan<<<128, 256, smem2>>>(hprev, cprev, Whh, out);
}